// round 1
// baseline (speedup 1.0000x reference)
#include <cuda_runtime.h>

#define LL 2
#define BB 32
#define SS 2048
#define DD 1024

// scratch (allocation-free rule: __device__ globals)
__device__ float g_bias[BB * DD];    // dec_proj + b_dec + b_enc, per (b,f)
__device__ float g_scores[BB * SS];  // pre-softmax scores

// ---------------- packed f32x2 helpers (FFMA2 path, sm_103a) ----------------
__device__ __forceinline__ unsigned long long pk2dup(float x) {
    unsigned long long r;
    asm("mov.b64 %0, {%1, %1};" : "=l"(r) : "f"(x));
    return r;
}
__device__ __forceinline__ void ffma2(unsigned long long& d, unsigned long long a,
                                      unsigned long long b) {
    asm("fma.rn.f32x2 %0, %1, %2, %0;" : "+l"(d) : "l"(a), "l"(b));
}
__device__ __forceinline__ float2 unpk2(unsigned long long v) {
    float2 r;
    asm("mov.b64 {%0, %1}, %2;" : "=f"(r.x), "=f"(r.y) : "l"(v));
    return r;
}

// ---------------- kernel 1: g_bias[b,f] = (dh[-1] @ W_dec)[b,f] + b_dec[f] + b_enc[f]
__global__ __launch_bounds__(256) void k_decproj(const float* __restrict__ dh,
                                                 const float* __restrict__ Wd,
                                                 const float* __restrict__ bd,
                                                 const float* __restrict__ be) {
    const int b = blockIdx.x;
    const int tid = threadIdx.x;
    __shared__ float h[DD];
    for (int k = tid; k < DD; k += 256) h[k] = dh[(LL - 1) * BB * DD + b * DD + k];
    __syncthreads();
    const int f0 = tid * 4;
    float a0 = 0.f, a1 = 0.f, a2 = 0.f, a3 = 0.f;
#pragma unroll 4
    for (int k = 0; k < DD; k++) {
        float4 w = *(const float4*)(Wd + (size_t)k * DD + f0);
        float hk = h[k];
        a0 += hk * w.x; a1 += hk * w.y; a2 += hk * w.z; a3 += hk * w.w;
    }
    g_bias[b * DD + f0 + 0] = a0 + bd[f0 + 0] + be[f0 + 0];
    g_bias[b * DD + f0 + 1] = a1 + bd[f0 + 1] + be[f0 + 1];
    g_bias[b * DD + f0 + 2] = a2 + bd[f0 + 2] + be[f0 + 2];
    g_bias[b * DD + f0 + 3] = a3 + bd[f0 + 3] + be[f0 + 3];
}

// ---------------- kernel 2: fused scores GEMM ----------------
// scores[b,s] = sum_f tanh( (E[b,s,:] @ W_enc)[f] + g_bias[b,f] ) * w_att[f]
// Tile: BM=128 (s), BN=128 (f), BK=16. 256 threads, 8x8 micro-tile as f32x2 pairs.
__global__ __launch_bounds__(256, 2) void k_scores(const float* __restrict__ E,
                                                   const float* __restrict__ We,
                                                   const float* __restrict__ wa) {
    const int b = blockIdx.y;
    const int s0 = blockIdx.x * 128;
    const float* Eb = E + (size_t)b * SS * DD;

    __shared__ float As[16][132];  // [k][m], padded to kill transpose-store conflicts
    __shared__ float Bs[16][128];  // [k][n]

    const int tid = threadIdx.x;
    const int tx = tid & 15;       // n direction
    const int ty = tid >> 4;       // m direction

    float psum[8];
#pragma unroll
    for (int i = 0; i < 8; i++) psum[i] = 0.f;

    for (int nt = 0; nt < 8; nt++) {
        const int f0 = nt * 128;
        unsigned long long acc[4][8];  // row pairs (2*i2, 2*i2+1) x 8 cols
#pragma unroll
        for (int i = 0; i < 4; i++)
#pragma unroll
            for (int j = 0; j < 8; j++) acc[i][j] = 0ULL;

        for (int kt = 0; kt < 64; kt++) {
            const int k0 = kt * 16;
            // A tile: 128 rows x 16 k, transposed into As[k][m]
#pragma unroll
            for (int it = 0; it < 2; it++) {
                int idx = it * 256 + tid;       // 0..511 float4s
                int row = idx >> 2;
                int k4 = (idx & 3) << 2;
                float4 v = *(const float4*)(Eb + (size_t)(s0 + row) * DD + k0 + k4);
                As[k4 + 0][row] = v.x;
                As[k4 + 1][row] = v.y;
                As[k4 + 2][row] = v.z;
                As[k4 + 3][row] = v.w;
            }
            // B tile: 16 k-rows x 128 f
#pragma unroll
            for (int it = 0; it < 2; it++) {
                int idx = it * 256 + tid;
                int kk = idx >> 5;
                int j4 = (idx & 31) << 2;
                *(float4*)(&Bs[kk][j4]) =
                    *(const float4*)(We + (size_t)(k0 + kk) * DD + f0 + j4);
            }
            __syncthreads();
#pragma unroll
            for (int kk = 0; kk < 16; kk++) {
                // A fragment: 8 rows as 4 packed f32x2 pairs (free pairing)
                const ulonglong2* ap = (const ulonglong2*)(&As[kk][ty * 8]);
                ulonglong2 a01 = ap[0], a23 = ap[1];
                unsigned long long av[4] = {a01.x, a01.y, a23.x, a23.y};
                // B fragment: 8 cols, each duplicated into both f32x2 lanes
                float bf[8];
                *(float4*)&bf[0] = *(const float4*)(&Bs[kk][tx * 8]);
                *(float4*)&bf[4] = *(const float4*)(&Bs[kk][tx * 8 + 4]);
                unsigned long long bd2[8];
#pragma unroll
                for (int j = 0; j < 8; j++) bd2[j] = pk2dup(bf[j]);
#pragma unroll
                for (int i = 0; i < 4; i++)
#pragma unroll
                    for (int j = 0; j < 8; j++) ffma2(acc[i][j], av[i], bd2[j]);
            }
            __syncthreads();
        }
        // epilogue: += tanh(c + bias[b,f]) * w_att[f], accumulated per row
#pragma unroll
        for (int j = 0; j < 8; j++) {
            int f = f0 + tx * 8 + j;
            float bias = g_bias[b * DD + f];
            float w = wa[f];
#pragma unroll
            for (int i2 = 0; i2 < 4; i2++) {
                float2 c = unpk2(acc[i2][j]);
                psum[2 * i2 + 0] += tanhf(c.x + bias) * w;
                psum[2 * i2 + 1] += tanhf(c.y + bias) * w;
            }
        }
    }
    // reduce across the 16 tx lanes (each half-warp segment owns 8 rows)
#pragma unroll
    for (int off = 8; off >= 1; off >>= 1)
#pragma unroll
        for (int i = 0; i < 8; i++)
            psum[i] += __shfl_down_sync(0xffffffffu, psum[i], off, 16);
    if (tx == 0) {
#pragma unroll
        for (int i = 0; i < 8; i++)
            g_scores[b * SS + s0 + ty * 8 + i] = psum[i];
    }
}

// ---------------- kernel 3: masked softmax over S per batch row ----------------
// (b_att is a uniform shift -> softmax-invariant, omitted)
__global__ __launch_bounds__(256) void k_softmax(const int* __restrict__ mask,
                                                 float* __restrict__ attn) {
    const int b = blockIdx.x;
    const int tid = threadIdx.x;
    __shared__ float sc[SS];
    __shared__ float red[256];
    float lmax = -3.4e38f;
    for (int s = tid; s < SS; s += 256) {
        float v = (mask[b * SS + s] == 0) ? -1e10f : g_scores[b * SS + s];
        sc[s] = v;
        lmax = fmaxf(lmax, v);
    }
    red[tid] = lmax;
    __syncthreads();
    for (int o = 128; o > 0; o >>= 1) {
        if (tid < o) red[tid] = fmaxf(red[tid], red[tid + o]);
        __syncthreads();
    }
    float m = red[0];
    __syncthreads();
    float lsum = 0.f;
    for (int s = tid; s < SS; s += 256) {
        float e = __expf(sc[s] - m);
        sc[s] = e;
        lsum += e;
    }
    red[tid] = lsum;
    __syncthreads();
    for (int o = 128; o > 0; o >>= 1) {
        if (tid < o) red[tid] += red[tid + o];
        __syncthreads();
    }
    float inv = 1.f / red[0];
    for (int s = tid; s < SS; s += 256) attn[b * SS + s] = sc[s] * inv;
}

// ---------------- kernel 4: context[b,d] = sum_s attn[b,s] * E[b,s,d] ----------------
__global__ __launch_bounds__(128) void k_context(const float* __restrict__ E,
                                                 const float* __restrict__ attn,
                                                 float* __restrict__ ctx) {
    const int b = blockIdx.y;
    const int d = blockIdx.x * 128 + threadIdx.x;
    __shared__ float a[SS];
    for (int s = threadIdx.x; s < SS; s += 128) a[s] = attn[b * SS + s];
    __syncthreads();
    const float* Eb = E + (size_t)b * SS * DD + d;
    float a0 = 0.f, a1 = 0.f, a2 = 0.f, a3 = 0.f;
#pragma unroll 4
    for (int s = 0; s < SS; s += 4) {
        a0 += a[s + 0] * Eb[(size_t)(s + 0) * DD];
        a1 += a[s + 1] * Eb[(size_t)(s + 1) * DD];
        a2 += a[s + 2] * Eb[(size_t)(s + 2) * DD];
        a3 += a[s + 3] * Eb[(size_t)(s + 3) * DD];
    }
    ctx[b * DD + d] = ((a0 + a1) + (a2 + a3));
}

extern "C" void kernel_launch(void* const* d_in, const int* in_sizes, int n_in,
                              void* d_out, int out_size) {
    const float* dh   = (const float*)d_in[0];  // [2,32,1024]
    const float* E    = (const float*)d_in[1];  // [32,2048,1024]
    const int*   mask = (const int*)d_in[2];    // [32,2048]
    const float* Wd   = (const float*)d_in[3];  // [1024,1024]
    const float* bd   = (const float*)d_in[4];  // [1024]
    const float* We   = (const float*)d_in[5];  // [1024,1024]
    const float* be   = (const float*)d_in[6];  // [1024]
    const float* wa   = (const float*)d_in[7];  // [1024,1]
    (void)d_in[8];                               // b_att: softmax-invariant

    float* out  = (float*)d_out;
    float* ctx  = out;            // context: B*D = 32768 floats
    float* attn = out + BB * DD;  // attn:    B*S = 65536 floats

    k_decproj<<<BB, 256>>>(dh, Wd, bd, be);
    dim3 g2(SS / 128, BB);
    k_scores<<<g2, 256>>>(E, We, wa);
    k_softmax<<<BB, 256>>>(mask, attn);
    dim3 g4(DD / 128, BB);
    k_context<<<g4, 128>>>(E, attn, ctx);
}

// round 3
// speedup vs baseline: 3.1329x; 3.1329x over previous
#include <cuda_runtime.h>
#include <cstdint>

#define LL 2
#define BB 32
#define SS 2048
#define DD 1024

// tcgen05 is only legal in arch-specific (sm_103a/sm_100a) compilation passes.
// The harness also emits a generic compute_103 PTX pass -> guard + fallback.
#if defined(__CUDA_ARCH_FEAT_SM103_ALL) || defined(__CUDA_ARCH_FEAT_SM100_ALL) || \
    defined(__CUDA_ARCH_SPECIFIC__) || defined(__CUDA_ARCH_FAMILY_SPECIFIC__)
#define TC_OK 1
#else
#define TC_OK 0
#endif

// scratch (allocation-free rule: __device__ globals)
__device__ float g_bias[BB * DD];    // dec_proj + b_dec + b_enc
__device__ float g_scores[BB * SS];  // pre-softmax scores
__device__ float g_Wt[DD * DD];      // W_enc transposed: Wt[f][k]

// ---------------- low-level helpers ----------------
__device__ __forceinline__ uint32_t smem_u32(const void* p) {
    uint32_t a;
    asm("{ .reg .u64 t; cvta.to.shared.u64 t, %1; cvt.u32.u64 %0, t; }"
        : "=r"(a) : "l"(p));
    return a;
}
__device__ __forceinline__ uint32_t elect1() {
    uint32_t p;
    asm volatile("{ .reg .pred p; elect.sync _|p, 0xFFFFFFFF; selp.b32 %0,1,0,p; }"
                 : "=r"(p));
    return p;
}
__device__ __forceinline__ float tf32hi(float x) {
    uint32_t u;
    asm("cvt.rna.tf32.f32 %0, %1;" : "=r"(u) : "f"(x));
    return __uint_as_float(u);
}
__device__ __forceinline__ void mbar_init(uint32_t a, uint32_t cnt) {
    asm volatile("mbarrier.init.shared.b64 [%0], %1;" :: "r"(a), "r"(cnt) : "memory");
}
__device__ __forceinline__ void mbar_wait(uint32_t a, int phase) {
    asm volatile(
        "{\n\t.reg .pred P;\n\t"
        "WL%=:\n\t"
        "mbarrier.try_wait.parity.acquire.cta.shared::cta.b64 P, [%0], %1, 0x989680;\n\t"
        "@P bra WD%=;\n\t"
        "bra WL%=;\n\t"
        "WD%=:\n\t}"
        :: "r"(a), "r"(phase) : "memory");
}
__device__ __forceinline__ uint64_t mkdesc(uint32_t addr) {
    const uint64_t base = (uint64_t(2) << 61) | (uint64_t(1) << 46) |
                          (uint64_t(64) << 32) | (uint64_t(1) << 16);  // SW128 K-major
    return base | ((uint64_t)(addr >> 4) & 0x3FFF);
}
#if TC_OK
__device__ __forceinline__ void mma_tf32(uint32_t d, uint64_t ad, uint64_t bd,
                                         uint32_t idesc, uint32_t en) {
    asm volatile(
        "{\n\t.reg .pred p;\n\tsetp.ne.u32 p, %4, 0;\n\t"
        "tcgen05.mma.cta_group::1.kind::tf32 [%0], %1, %2, %3, {%5,%5,%5,%5}, p;\n\t}"
        :: "r"(d), "l"(ad), "l"(bd), "r"(idesc), "r"(en), "r"(0u) : "memory");
}
__device__ __forceinline__ void tc_commit(uint32_t mbar) {
    asm volatile(
        "tcgen05.commit.cta_group::1.mbarrier::arrive::one.shared::cluster.b64 [%0];"
        :: "r"(mbar) : "memory");
}
#endif

#define SWZ(o) ((o) ^ (((o) >> 3) & 0x70))

// fast accurate tanh: 1 - 2/(e^{2x}+1); abs err ~1e-6
__device__ __forceinline__ float tanh_fast(float x) {
    return 1.f - __fdividef(2.f, __expf(2.f * x) + 1.f);
}

// ---------------- kernel 0: transpose W_enc -> Wt[f][k] ----------------
__global__ __launch_bounds__(256) void k_transpose(const float* __restrict__ W) {
    __shared__ float t[32][33];
    const int x = blockIdx.x * 32 + threadIdx.x;  // f
    const int y0 = blockIdx.y * 32;               // k
#pragma unroll
    for (int j = 0; j < 4; j++)
        t[threadIdx.y + j * 8][threadIdx.x] = W[(size_t)(y0 + threadIdx.y + j * 8) * DD + x];
    __syncthreads();
    const int f = blockIdx.x * 32;
#pragma unroll
    for (int j = 0; j < 4; j++)
        g_Wt[(size_t)(f + threadIdx.y + j * 8) * DD + y0 + threadIdx.x] =
            t[threadIdx.x][threadIdx.y + j * 8];
}

// ---------------- kernel 1: g_bias = dh[-1] @ W_dec + b_dec + b_enc ----------------
__global__ __launch_bounds__(256) void k_decproj(const float* __restrict__ dh,
                                                 const float* __restrict__ Wd,
                                                 const float* __restrict__ bd,
                                                 const float* __restrict__ be) {
    const int b = blockIdx.x;
    const int tid = threadIdx.x;
    __shared__ float h[DD];
    for (int k = tid; k < DD; k += 256) h[k] = dh[(LL - 1) * BB * DD + b * DD + k];
    __syncthreads();
    const int f0 = tid * 4;
    float a0 = 0.f, a1 = 0.f, a2 = 0.f, a3 = 0.f;
#pragma unroll 4
    for (int k = 0; k < DD; k++) {
        float4 w = *(const float4*)(Wd + (size_t)k * DD + f0);
        float hk = h[k];
        a0 += hk * w.x; a1 += hk * w.y; a2 += hk * w.z; a3 += hk * w.w;
    }
    g_bias[b * DD + f0 + 0] = a0 + bd[f0 + 0] + be[f0 + 0];
    g_bias[b * DD + f0 + 1] = a1 + bd[f0 + 1] + be[f0 + 1];
    g_bias[b * DD + f0 + 2] = a2 + bd[f0 + 2] + be[f0 + 2];
    g_bias[b * DD + f0 + 3] = a3 + bd[f0 + 3] + be[f0 + 3];
}

// ---------------- kernel 2: fused scores via tcgen05 3xTF32 ----------------
// D[s=128, f=256] accumulated over K in TMEM, 4 f-passes, epilogue fuses
// tanh(d + bias)*w_att and reduces over f. 2-stage smem pipeline.
#define STAGE_BYTES 98304
#define OFF_A_HI 0
#define OFF_A_LO 16384
#define OFF_B_HI 32768
#define OFF_B_LO 65536
#define CTL_BYTES 4096
#define SMEM_DYN (CTL_BYTES + 2 * STAGE_BYTES)

static constexpr uint32_t IDESC_TF32 =
    (1u << 4) | (2u << 7) | (2u << 10) | ((256u / 8) << 17) | ((128u / 16) << 24);

__global__ __launch_bounds__(256, 1) void k_scores(const float* __restrict__ E,
                                                   const float* __restrict__ wa) {
#if TC_OK
    extern __shared__ char sm[];
    const uint32_t smb = smem_u32(sm);
    const int tid = threadIdx.x;
    const int wid = tid >> 5;
    const int b = blockIdx.y;
    const int s0 = blockIdx.x * 128;

    // control region
    const uint32_t mbar0 = smb + 16;
    const uint32_t mbar1 = smb + 24;
    float* biasS = (float*)(sm + 1024);
    float* waS = (float*)(sm + 2048);
    float* red = (float*)(sm + 3072);

    if (wid == 0)
        asm volatile("tcgen05.alloc.cta_group::1.sync.aligned.shared::cta.b32 [%0], %1;"
                     :: "r"(smb), "r"(256) : "memory");
    if (tid == 0) { mbar_init(mbar0, 1); mbar_init(mbar1, 1); }
    __syncthreads();
    uint32_t tmem;
    asm("ld.shared.b32 %0, [%1];" : "=r"(tmem) : "r"(smb));

    int ph0 = 0, ph1 = 0;
    float acc = 0.f;
    const float* Eb = E + ((size_t)b * SS + s0) * DD;
    const int wg = wid >> 2, w4 = wid & 3, lane = tid & 31;

    for (int p = 0; p < 4; p++) {
        const int f0 = p * 256;
        for (int c = 0; c < 32; c++) {
            const int g = p * 32 + c;
            const int st = g & 1;
            if (g >= 2) {
                if (st == 0) { mbar_wait(mbar0, ph0); ph0 ^= 1; }
                else         { mbar_wait(mbar1, ph1); ph1 ^= 1; }
            }
            char* stg = sm + CTL_BYTES + st * STAGE_BYTES;
            char* sAh = stg + OFF_A_HI;
            char* sAl = stg + OFF_A_LO;
            char* sBh = stg + OFF_B_HI;
            char* sBl = stg + OFF_B_LO;
            const int k0 = c * 32;
            // ---- A tile: E[s0..s0+127, k0..k0+31], hi/lo split, SW128 ----
#pragma unroll
            for (int i = 0; i < 4; i++) {
                int idx = tid + i * 256;
                int row = idx >> 3, c16 = idx & 7;
                float4 v = *(const float4*)(Eb + (size_t)row * DD + k0 + c16 * 4);
                float4 h, l;
                h.x = tf32hi(v.x); h.y = tf32hi(v.y); h.z = tf32hi(v.z); h.w = tf32hi(v.w);
                l.x = v.x - h.x; l.y = v.y - h.y; l.z = v.z - h.z; l.w = v.w - h.w;
                uint32_t o = SWZ((uint32_t)(row * 128 + c16 * 16));
                *(float4*)(sAh + o) = h;
                *(float4*)(sAl + o) = l;
            }
            // ---- B tile: Wt[f0..f0+255, k0..k0+31], hi/lo split, SW128 ----
            const float* Wb = g_Wt + (size_t)f0 * DD + k0;
#pragma unroll
            for (int i = 0; i < 8; i++) {
                int idx = tid + i * 256;
                int n = idx >> 3, c16 = idx & 7;
                float4 v = *(const float4*)(Wb + (size_t)n * DD + c16 * 4);
                float4 h, l;
                h.x = tf32hi(v.x); h.y = tf32hi(v.y); h.z = tf32hi(v.z); h.w = tf32hi(v.w);
                l.x = v.x - h.x; l.y = v.y - h.y; l.z = v.z - h.z; l.w = v.w - h.w;
                uint32_t o = SWZ((uint32_t)(n * 128 + c16 * 16));
                *(float4*)(sBh + o) = h;
                *(float4*)(sBl + o) = l;
            }
            asm volatile("fence.proxy.async.shared::cta;" ::: "memory");
            __syncthreads();
            if (wid == 0 && elect1()) {
                if (c == 0)
                    asm volatile("tcgen05.fence::after_thread_sync;" ::: "memory");
                uint64_t ah = mkdesc(smb + CTL_BYTES + st * STAGE_BYTES + OFF_A_HI);
                uint64_t al = mkdesc(smb + CTL_BYTES + st * STAGE_BYTES + OFF_A_LO);
                uint64_t bh = mkdesc(smb + CTL_BYTES + st * STAGE_BYTES + OFF_B_HI);
                uint64_t bl = mkdesc(smb + CTL_BYTES + st * STAGE_BYTES + OFF_B_LO);
#pragma unroll
                for (int kk = 0; kk < 4; kk++) {
                    mma_tf32(tmem, ah + 2 * kk, bh + 2 * kk, IDESC_TF32,
                             (c > 0) || (kk > 0));
                    mma_tf32(tmem, ah + 2 * kk, bl + 2 * kk, IDESC_TF32, 1);
                    mma_tf32(tmem, al + 2 * kk, bh + 2 * kk, IDESC_TF32, 1);
                }
                tc_commit(st == 0 ? mbar0 : mbar1);
            }
        }
        // ---- pass epilogue ----
        biasS[tid] = g_bias[b * DD + f0 + tid];
        waS[tid] = wa[f0 + tid];
        mbar_wait(mbar1, ph1);  // last chunk (g odd) commit; do NOT flip
        asm volatile("tcgen05.fence::after_thread_sync;" ::: "memory");
        __syncthreads();
        const int colbase = wg * 128;
#pragma unroll
        for (int cb = 0; cb < 4; cb++) {
            uint32_t r[32];
            asm volatile(
                "tcgen05.ld.sync.aligned.32x32b.x32.b32 "
                "{%0, %1, %2, %3, %4, %5, %6, %7, "
                " %8, %9, %10, %11, %12, %13, %14, %15, "
                " %16, %17, %18, %19, %20, %21, %22, %23, "
                " %24, %25, %26, %27, %28, %29, %30, %31}, [%32];"
                : "=r"(r[0]), "=r"(r[1]), "=r"(r[2]), "=r"(r[3]),
                  "=r"(r[4]), "=r"(r[5]), "=r"(r[6]), "=r"(r[7]),
                  "=r"(r[8]), "=r"(r[9]), "=r"(r[10]), "=r"(r[11]),
                  "=r"(r[12]), "=r"(r[13]), "=r"(r[14]), "=r"(r[15]),
                  "=r"(r[16]), "=r"(r[17]), "=r"(r[18]), "=r"(r[19]),
                  "=r"(r[20]), "=r"(r[21]), "=r"(r[22]), "=r"(r[23]),
                  "=r"(r[24]), "=r"(r[25]), "=r"(r[26]), "=r"(r[27]),
                  "=r"(r[28]), "=r"(r[29]), "=r"(r[30]), "=r"(r[31])
                : "r"(tmem + colbase + cb * 32));
            asm volatile("tcgen05.wait::ld.sync.aligned;" ::: "memory");
#pragma unroll
            for (int j = 0; j < 32; j++) {
                int f = colbase + cb * 32 + j;
                float x = __uint_as_float(r[j]) + biasS[f];
                acc += tanh_fast(x) * waS[f];
            }
        }
        asm volatile("tcgen05.fence::before_thread_sync;" ::: "memory");
        __syncthreads();  // all LDTM done before next pass re-inits D
    }
    // combine the two column-halves per row and store
    red[wg * 128 + w4 * 32 + lane] = acc;
    __syncthreads();
    if (tid < 128) g_scores[b * SS + s0 + tid] = red[tid] + red[tid + 128];
    __syncthreads();
    if (wid == 0)
        asm volatile("tcgen05.dealloc.cta_group::1.sync.aligned.b32 %0, %1;"
                     :: "r"(tmem), "r"(256));
#else
    // Generic-PTX fallback (never executes on sm_103a: exact cubin is loaded).
    const int b = blockIdx.y;
    const int s = blockIdx.x * 128 + (threadIdx.x >> 1);
    const int fh = (threadIdx.x & 1) * 512;
    const float* Er = E + ((size_t)b * SS + s) * DD;
    float acc = 0.f;
    for (int f = fh; f < fh + 512; f++) {
        const float* Wr = g_Wt + (size_t)f * DD;
        float e = g_bias[b * DD + f];
        for (int k = 0; k < DD; k++) e += Er[k] * Wr[k];
        acc += tanhf(e) * wa[f];
    }
    acc += __shfl_xor_sync(0xffffffffu, acc, 1);
    if ((threadIdx.x & 1) == 0) g_scores[b * SS + s] = acc;
#endif
}

// ---------------- kernel 3: masked softmax over S ----------------
__global__ __launch_bounds__(256) void k_softmax(const int* __restrict__ mask,
                                                 float* __restrict__ attn) {
    const int b = blockIdx.x;
    const int tid = threadIdx.x;
    __shared__ float sc[SS];
    __shared__ float red[256];
    float lmax = -3.4e38f;
    for (int s = tid; s < SS; s += 256) {
        float v = (mask[b * SS + s] == 0) ? -1e10f : g_scores[b * SS + s];
        sc[s] = v;
        lmax = fmaxf(lmax, v);
    }
    red[tid] = lmax;
    __syncthreads();
    for (int o = 128; o > 0; o >>= 1) {
        if (tid < o) red[tid] = fmaxf(red[tid], red[tid + o]);
        __syncthreads();
    }
    float m = red[0];
    __syncthreads();
    float lsum = 0.f;
    for (int s = tid; s < SS; s += 256) {
        float e = __expf(sc[s] - m);
        sc[s] = e;
        lsum += e;
    }
    red[tid] = lsum;
    __syncthreads();
    for (int o = 128; o > 0; o >>= 1) {
        if (tid < o) red[tid] += red[tid + o];
        __syncthreads();
    }
    float inv = 1.f / red[0];
    for (int s = tid; s < SS; s += 256) attn[b * SS + s] = sc[s] * inv;
}

// ---------------- kernel 4: context[b,d] = sum_s attn[b,s]*E[b,s,d] ----------------
// 256 threads: two 1024-length s-halves per (b, 128-d chunk) for 2x MLP.
__global__ __launch_bounds__(256) void k_context(const float* __restrict__ E,
                                                 const float* __restrict__ attn,
                                                 float* __restrict__ ctx) {
    const int b = blockIdx.y;
    const int d = blockIdx.x * 128 + (threadIdx.x & 127);
    const int half = threadIdx.x >> 7;
    __shared__ float a[SS];
    __shared__ float red[256];
    for (int s = threadIdx.x; s < SS; s += 256) a[s] = attn[b * SS + s];
    __syncthreads();
    const float* Eb = E + ((size_t)b * SS + half * 1024) * DD + d;
    float acc[8];
#pragma unroll
    for (int j = 0; j < 8; j++) acc[j] = 0.f;
    for (int s = 0; s < 1024; s += 8) {
#pragma unroll
        for (int j = 0; j < 8; j++)
            acc[j] += a[half * 1024 + s + j] * Eb[(size_t)(s + j) * DD];
    }
    float t = ((acc[0] + acc[1]) + (acc[2] + acc[3])) +
              ((acc[4] + acc[5]) + (acc[6] + acc[7]));
    red[threadIdx.x] = t;
    __syncthreads();
    if (half == 0) ctx[b * DD + d] = red[threadIdx.x] + red[threadIdx.x + 128];
}

extern "C" void kernel_launch(void* const* d_in, const int* in_sizes, int n_in,
                              void* d_out, int out_size) {
    const float* dh   = (const float*)d_in[0];  // [2,32,1024]
    const float* E    = (const float*)d_in[1];  // [32,2048,1024]
    const int*   mask = (const int*)d_in[2];    // [32,2048]
    const float* Wd   = (const float*)d_in[3];  // [1024,1024]
    const float* bd   = (const float*)d_in[4];  // [1024]
    const float* We   = (const float*)d_in[5];  // [1024,1024]
    const float* be   = (const float*)d_in[6];  // [1024]
    const float* wa   = (const float*)d_in[7];  // [1024,1]
    (void)d_in[8];                               // b_att: softmax-invariant

    float* out  = (float*)d_out;
    float* ctx  = out;            // context: B*D
    float* attn = out + BB * DD;  // attn:    B*S

    cudaFuncSetAttribute(k_scores, cudaFuncAttributeMaxDynamicSharedMemorySize,
                         SMEM_DYN);

    dim3 gt(DD / 32, DD / 32);
    k_transpose<<<gt, dim3(32, 8)>>>(We);
    k_decproj<<<BB, 256>>>(dh, Wd, bd, be);
    dim3 g2(SS / 128, BB);
    k_scores<<<g2, 256, SMEM_DYN>>>(E, wa);
    k_softmax<<<BB, 256>>>(mask, attn);
    dim3 g4(DD / 128, BB);
    k_context<<<g4, 256>>>(E, attn, ctx);
}

// round 5
// speedup vs baseline: 4.4029x; 1.4054x over previous
#include <cuda_runtime.h>
#include <cuda_fp16.h>
#include <cstdint>
#include <cstring>

#define LL 2
#define BB 32
#define SS 2048
#define DD 1024

#if defined(__CUDA_ARCH_FEAT_SM103_ALL) || defined(__CUDA_ARCH_FEAT_SM100_ALL) || \
    defined(__CUDA_ARCH_SPECIFIC__) || defined(__CUDA_ARCH_FAMILY_SPECIFIC__)
#define TC_OK 1
#else
#define TC_OK 0
#endif

// scratch (allocation-free rule: __device__ globals)
__device__ float g_bias[BB * DD];        // dec_proj + b_dec + b_enc
__device__ float g_scores[BB * SS];      // pre-softmax scores
__device__ __half g_Whi[DD * DD];        // W_enc^T hi fp16, [f][k]
__device__ __half g_Wlo[DD * DD];        // W_enc^T lo fp16, [f][k]
__device__ float g_cpart[8 * BB * DD];   // context partials over s-chunks

// ---------------- low-level helpers ----------------
__device__ __forceinline__ uint32_t h2u(__half2 h) {
    uint32_t u;
    memcpy(&u, &h, 4);
    return u;
}
__device__ __forceinline__ uint32_t smem_u32(const void* p) {
    uint32_t a;
    asm("{ .reg .u64 t; cvta.to.shared.u64 t, %1; cvt.u32.u64 %0, t; }"
        : "=r"(a) : "l"(p));
    return a;
}
__device__ __forceinline__ uint32_t elect1() {
    uint32_t p;
    asm volatile("{ .reg .pred p; elect.sync _|p, 0xFFFFFFFF; selp.b32 %0,1,0,p; }"
                 : "=r"(p));
    return p;
}
__device__ __forceinline__ void mbar_init(uint32_t a, uint32_t cnt) {
    asm volatile("mbarrier.init.shared.b64 [%0], %1;" :: "r"(a), "r"(cnt) : "memory");
}
__device__ __forceinline__ void mbar_wait(uint32_t a, int phase) {
    asm volatile(
        "{\n\t.reg .pred P;\n\t"
        "WL%=:\n\t"
        "mbarrier.try_wait.parity.acquire.cta.shared::cta.b64 P, [%0], %1, 0x989680;\n\t"
        "@P bra WD%=;\n\t"
        "bra WL%=;\n\t"
        "WD%=:\n\t}"
        :: "r"(a), "r"(phase) : "memory");
}
__device__ __forceinline__ uint64_t mkdesc(uint32_t addr) {
    const uint64_t base = (uint64_t(2) << 61) | (uint64_t(1) << 46) |
                          (uint64_t(64) << 32) | (uint64_t(1) << 16);  // SW128 K-major
    return base | ((uint64_t)(addr >> 4) & 0x3FFF);
}
#if TC_OK
__device__ __forceinline__ void mma_f16(uint32_t d, uint64_t ad, uint64_t bd,
                                        uint32_t idesc, uint32_t en) {
    asm volatile(
        "{\n\t.reg .pred p;\n\tsetp.ne.u32 p, %4, 0;\n\t"
        "tcgen05.mma.cta_group::1.kind::f16 [%0], %1, %2, %3, {%5,%5,%5,%5}, p;\n\t}"
        :: "r"(d), "l"(ad), "l"(bd), "r"(idesc), "r"(en), "r"(0u) : "memory");
}
__device__ __forceinline__ void tc_commit(uint32_t mbar) {
    asm volatile(
        "tcgen05.commit.cta_group::1.mbarrier::arrive::one.shared::cluster.b64 [%0];"
        :: "r"(mbar) : "memory");
}
#endif

#define SWZ(o) ((o) ^ (((o) >> 3) & 0x70))

__device__ __forceinline__ float tanh_fast(float x) {
    return 1.f - __fdividef(2.f, __expf(2.f * x) + 1.f);
}

// ---------------- kernel 0: W_enc -> transposed fp16 hi/lo split ----------------
__global__ __launch_bounds__(256) void k_wsplit(const float* __restrict__ W) {
    __shared__ float t[32][33];
    const int x = blockIdx.x * 32 + threadIdx.x;  // f
    const int y0 = blockIdx.y * 32;               // k
#pragma unroll
    for (int j = 0; j < 4; j++)
        t[threadIdx.y + j * 8][threadIdx.x] = W[(size_t)(y0 + threadIdx.y + j * 8) * DD + x];
    __syncthreads();
    const int f0 = blockIdx.x * 32;
#pragma unroll
    for (int j = 0; j < 4; j++) {
        float v = t[threadIdx.x][threadIdx.y + j * 8];
        __half h = __float2half_rn(v);
        __half l = __float2half_rn(v - __half2float(h));
        size_t o = (size_t)(f0 + threadIdx.y + j * 8) * DD + y0 + threadIdx.x;
        g_Whi[o] = h;
        g_Wlo[o] = l;
    }
}

// ---------------- kernel 1: g_bias = dh[-1] @ W_dec + b_dec + b_enc ----------------
__global__ __launch_bounds__(256) void k_decproj(const float* __restrict__ dh,
                                                 const float* __restrict__ Wd,
                                                 const float* __restrict__ bd,
                                                 const float* __restrict__ be) {
    const int b = blockIdx.x;
    const int tid = threadIdx.x;
    __shared__ float h[DD];
    for (int k = tid; k < DD; k += 256) h[k] = dh[(LL - 1) * BB * DD + b * DD + k];
    __syncthreads();
    const int f0 = tid * 4;
    float a0 = 0.f, a1 = 0.f, a2 = 0.f, a3 = 0.f;
#pragma unroll 4
    for (int k = 0; k < DD; k++) {
        float4 w = *(const float4*)(Wd + (size_t)k * DD + f0);
        float hk = h[k];
        a0 += hk * w.x; a1 += hk * w.y; a2 += hk * w.z; a3 += hk * w.w;
    }
    g_bias[b * DD + f0 + 0] = a0 + bd[f0 + 0] + be[f0 + 0];
    g_bias[b * DD + f0 + 1] = a1 + bd[f0 + 1] + be[f0 + 1];
    g_bias[b * DD + f0 + 2] = a2 + bd[f0 + 2] + be[f0 + 2];
    g_bias[b * DD + f0 + 3] = a3 + bd[f0 + 3] + be[f0 + 3];
}

// ---------------- kernel 2: fused scores via tcgen05 3xFP16 ----------------
// D[s=128, f=256] in TMEM, K=64 per chunk (16 chunks/pass), 4 f-passes.
// Epilogue fuses tanh(d + bias)*w_att and reduces over f. 2-stage pipeline.
#define STAGE_BYTES 98304
#define OFF_A_HI 0
#define OFF_A_LO 16384
#define OFF_B_HI 32768
#define OFF_B_LO 65536
#define CTL_BYTES 4096
#define SMEM_DYN (CTL_BYTES + 2 * STAGE_BYTES)

#if TC_OK
static constexpr uint32_t IDESC_F16 =
    (1u << 4) | ((256u / 8) << 17) | ((128u / 16) << 24);  // fp16 in, f32 acc
#endif

__global__ __launch_bounds__(256, 1) void k_scores(const float* __restrict__ E,
                                                   const float* __restrict__ wa) {
#if TC_OK
    extern __shared__ char sm[];
    const uint32_t smb = smem_u32(sm);
    const int tid = threadIdx.x;
    const int wid = tid >> 5;
    const int b = blockIdx.y;
    const int s0 = blockIdx.x * 128;

    const uint32_t mbar0 = smb + 16;
    const uint32_t mbar1 = smb + 24;
    float* biasS = (float*)(sm + 1024);
    float* waS = (float*)(sm + 2048);
    float* red = (float*)(sm + 3072);

    if (wid == 0)
        asm volatile("tcgen05.alloc.cta_group::1.sync.aligned.shared::cta.b32 [%0], %1;"
                     :: "r"(smb), "r"(256) : "memory");
    if (tid == 0) { mbar_init(mbar0, 1); mbar_init(mbar1, 1); }
    __syncthreads();
    uint32_t tmem;
    asm("ld.shared.b32 %0, [%1];" : "=r"(tmem) : "r"(smb));

    int ph0 = 0, ph1 = 0;
    float acc = 0.f;
    const float* Eb = E + ((size_t)b * SS + s0) * DD;
    const int wg = wid >> 2, w4 = wid & 3, lane = tid & 31;

    for (int p = 0; p < 4; p++) {
        const int f0 = p * 256;
        for (int c = 0; c < 16; c++) {
            const int g = p * 16 + c;
            const int st = g & 1;
            if (g >= 2) {
                if (st == 0) { mbar_wait(mbar0, ph0); ph0 ^= 1; }
                else         { mbar_wait(mbar1, ph1); ph1 ^= 1; }
            }
            char* stg = sm + CTL_BYTES + st * STAGE_BYTES;
            const int k0 = c * 64;
            // ---- A tile: E[s0..s0+127, k0..k0+63] -> fp16 hi/lo, SW128 ----
            // 128 rows x 8 groups of 8 floats; 4 groups per thread.
#pragma unroll
            for (int i = 0; i < 4; i++) {
                int idx = tid + i * 256;
                int row = idx >> 3, grp = idx & 7;
                const float* src = Eb + (size_t)row * DD + k0 + grp * 8;
                float4 v0 = *(const float4*)(src);
                float4 v1 = *(const float4*)(src + 4);
                __half2 h0 = __floats2half2_rn(v0.x, v0.y);
                __half2 h1 = __floats2half2_rn(v0.z, v0.w);
                __half2 h2 = __floats2half2_rn(v1.x, v1.y);
                __half2 h3 = __floats2half2_rn(v1.z, v1.w);
                float2 f0v = __half22float2(h0), f1v = __half22float2(h1);
                float2 f2v = __half22float2(h2), f3v = __half22float2(h3);
                __half2 l0 = __floats2half2_rn(v0.x - f0v.x, v0.y - f0v.y);
                __half2 l1 = __floats2half2_rn(v0.z - f1v.x, v0.w - f1v.y);
                __half2 l2 = __floats2half2_rn(v1.x - f2v.x, v1.y - f2v.y);
                __half2 l3 = __floats2half2_rn(v1.z - f3v.x, v1.w - f3v.y);
                uint32_t o = SWZ((uint32_t)(row * 128 + grp * 16));
                *(uint4*)(stg + OFF_A_HI + o) =
                    make_uint4(h2u(h0), h2u(h1), h2u(h2), h2u(h3));
                *(uint4*)(stg + OFF_A_LO + o) =
                    make_uint4(h2u(l0), h2u(l1), h2u(l2), h2u(l3));
            }
            // ---- B tiles: pre-split fp16, pure copy. 256 rows x 8 units ----
#pragma unroll
            for (int i = 0; i < 8; i++) {
                int idx = tid + i * 256;
                int row = idx >> 3, grp = idx & 7;
                size_t go = (size_t)(f0 + row) * DD + k0 + grp * 8;
                uint32_t o = SWZ((uint32_t)(row * 128 + grp * 16));
                *(uint4*)(stg + OFF_B_HI + o) = *(const uint4*)(g_Whi + go);
                *(uint4*)(stg + OFF_B_LO + o) = *(const uint4*)(g_Wlo + go);
            }
            asm volatile("fence.proxy.async.shared::cta;" ::: "memory");
            __syncthreads();
            if (wid == 0 && elect1()) {
                if (c == 0)
                    asm volatile("tcgen05.fence::after_thread_sync;" ::: "memory");
                uint32_t sb = smb + CTL_BYTES + st * STAGE_BYTES;
                uint64_t ah = mkdesc(sb + OFF_A_HI);
                uint64_t al = mkdesc(sb + OFF_A_LO);
                uint64_t bh = mkdesc(sb + OFF_B_HI);
                uint64_t bl = mkdesc(sb + OFF_B_LO);
#pragma unroll
                for (int kk = 0; kk < 4; kk++) {  // K=16 fp16 per step = +2 desc units
                    mma_f16(tmem, ah + 2 * kk, bh + 2 * kk, IDESC_F16,
                            (c > 0) || (kk > 0));
                    mma_f16(tmem, ah + 2 * kk, bl + 2 * kk, IDESC_F16, 1);
                    mma_f16(tmem, al + 2 * kk, bh + 2 * kk, IDESC_F16, 1);
                }
                tc_commit(st == 0 ? mbar0 : mbar1);
            }
        }
        // ---- pass epilogue ----
        biasS[tid] = g_bias[b * DD + f0 + tid];
        waS[tid] = wa[f0 + tid];
        mbar_wait(mbar1, ph1);  // last chunk (c=15, stage 1) commit; no flip
        asm volatile("tcgen05.fence::after_thread_sync;" ::: "memory");
        __syncthreads();
        const int colbase = wg * 128;
#pragma unroll
        for (int cb = 0; cb < 4; cb++) {
            uint32_t r[32];
            asm volatile(
                "tcgen05.ld.sync.aligned.32x32b.x32.b32 "
                "{%0, %1, %2, %3, %4, %5, %6, %7, "
                " %8, %9, %10, %11, %12, %13, %14, %15, "
                " %16, %17, %18, %19, %20, %21, %22, %23, "
                " %24, %25, %26, %27, %28, %29, %30, %31}, [%32];"
                : "=r"(r[0]), "=r"(r[1]), "=r"(r[2]), "=r"(r[3]),
                  "=r"(r[4]), "=r"(r[5]), "=r"(r[6]), "=r"(r[7]),
                  "=r"(r[8]), "=r"(r[9]), "=r"(r[10]), "=r"(r[11]),
                  "=r"(r[12]), "=r"(r[13]), "=r"(r[14]), "=r"(r[15]),
                  "=r"(r[16]), "=r"(r[17]), "=r"(r[18]), "=r"(r[19]),
                  "=r"(r[20]), "=r"(r[21]), "=r"(r[22]), "=r"(r[23]),
                  "=r"(r[24]), "=r"(r[25]), "=r"(r[26]), "=r"(r[27]),
                  "=r"(r[28]), "=r"(r[29]), "=r"(r[30]), "=r"(r[31])
                : "r"(tmem + colbase + cb * 32));
            asm volatile("tcgen05.wait::ld.sync.aligned;" ::: "memory");
#pragma unroll
            for (int j = 0; j < 32; j++) {
                int f = colbase + cb * 32 + j;
                float x = __uint_as_float(r[j]) + biasS[f];
                acc += tanh_fast(x) * waS[f];
            }
        }
        asm volatile("tcgen05.fence::before_thread_sync;" ::: "memory");
        __syncthreads();  // all LDTM done before next pass re-inits D
    }
    red[wg * 128 + w4 * 32 + lane] = acc;
    __syncthreads();
    if (tid < 128) g_scores[b * SS + s0 + tid] = red[tid] + red[tid + 128];
    __syncthreads();
    if (wid == 0)
        asm volatile("tcgen05.dealloc.cta_group::1.sync.aligned.b32 %0, %1;"
                     :: "r"(tmem), "r"(256));
#else
    // Generic-PTX fallback (never executes: exact sm_103a cubin is loaded).
    const int b = blockIdx.y;
    const int s = blockIdx.x * 128 + (threadIdx.x >> 1);
    const int fh = (threadIdx.x & 1) * 512;
    const float* Er = E + ((size_t)b * SS + s) * DD;
    float acc = 0.f;
    for (int f = fh; f < fh + 512; f++) {
        float e = g_bias[b * DD + f];
        for (int k = 0; k < DD; k++)
            e += Er[k] * (__half2float(g_Whi[(size_t)f * DD + k]) +
                          __half2float(g_Wlo[(size_t)f * DD + k]));
        acc += tanhf(e) * wa[f];
    }
    acc += __shfl_xor_sync(0xffffffffu, acc, 1);
    if ((threadIdx.x & 1) == 0) g_scores[b * SS + s] = acc;
#endif
}

// ---------------- kernel 3: masked softmax over S ----------------
__global__ __launch_bounds__(256) void k_softmax(const int* __restrict__ mask,
                                                 float* __restrict__ attn) {
    const int b = blockIdx.x;
    const int tid = threadIdx.x;
    __shared__ float sc[SS];
    __shared__ float red[256];
    float lmax = -3.4e38f;
    for (int s = tid; s < SS; s += 256) {
        float v = (mask[b * SS + s] == 0) ? -1e10f : g_scores[b * SS + s];
        sc[s] = v;
        lmax = fmaxf(lmax, v);
    }
    red[tid] = lmax;
    __syncthreads();
    for (int o = 128; o > 0; o >>= 1) {
        if (tid < o) red[tid] = fmaxf(red[tid], red[tid + o]);
        __syncthreads();
    }
    float m = red[0];
    __syncthreads();
    float lsum = 0.f;
    for (int s = tid; s < SS; s += 256) {
        float e = __expf(sc[s] - m);
        sc[s] = e;
        lsum += e;
    }
    red[tid] = lsum;
    __syncthreads();
    for (int o = 128; o > 0; o >>= 1) {
        if (tid < o) red[tid] += red[tid + o];
        __syncthreads();
    }
    float inv = 1.f / red[0];
    for (int s = tid; s < SS; s += 256) attn[b * SS + s] = sc[s] * inv;
}

// ---------------- kernel 4a: context partials over 8 s-chunks ----------------
__global__ __launch_bounds__(128) void k_context_part(const float* __restrict__ E,
                                                      const float* __restrict__ attn) {
    const int b = blockIdx.y;
    const int sc = blockIdx.z;
    const int d = blockIdx.x * 128 + threadIdx.x;
    const int s0 = sc * 256;
    __shared__ float a[256];
    for (int i = threadIdx.x; i < 256; i += 128) a[i] = attn[b * SS + s0 + i];
    __syncthreads();
    const float* Eb = E + ((size_t)b * SS + s0) * DD + d;
    float acc[8];
#pragma unroll
    for (int j = 0; j < 8; j++) acc[j] = 0.f;
    for (int s = 0; s < 256; s += 8) {
#pragma unroll
        for (int j = 0; j < 8; j++)
            acc[j] += a[s + j] * Eb[(size_t)(s + j) * DD];
    }
    g_cpart[(sc * BB + b) * DD + d] =
        ((acc[0] + acc[1]) + (acc[2] + acc[3])) +
        ((acc[4] + acc[5]) + (acc[6] + acc[7]));
}

// ---------------- kernel 4b: reduce partials ----------------
__global__ __launch_bounds__(256) void k_context_red(float* __restrict__ ctx) {
    const int b = blockIdx.x;
    for (int d = threadIdx.x; d < DD; d += 256) {
        float s = 0.f;
#pragma unroll
        for (int sc = 0; sc < 8; sc++) s += g_cpart[(sc * BB + b) * DD + d];
        ctx[b * DD + d] = s;
    }
}

extern "C" void kernel_launch(void* const* d_in, const int* in_sizes, int n_in,
                              void* d_out, int out_size) {
    const float* dh   = (const float*)d_in[0];  // [2,32,1024]
    const float* E    = (const float*)d_in[1];  // [32,2048,1024]
    const int*   mask = (const int*)d_in[2];    // [32,2048]
    const float* Wd   = (const float*)d_in[3];  // [1024,1024]
    const float* bd   = (const float*)d_in[4];  // [1024]
    const float* We   = (const float*)d_in[5];  // [1024,1024]
    const float* be   = (const float*)d_in[6];  // [1024]
    const float* wa   = (const float*)d_in[7];  // [1024,1]
    (void)d_in[8];                               // b_att: softmax-invariant

    float* out  = (float*)d_out;
    float* ctx  = out;            // context: B*D
    float* attn = out + BB * DD;  // attn:    B*S

    cudaFuncSetAttribute(k_scores, cudaFuncAttributeMaxDynamicSharedMemorySize,
                         SMEM_DYN);

    dim3 gt(DD / 32, DD / 32);
    k_wsplit<<<gt, dim3(32, 8)>>>(We);
    k_decproj<<<BB, 256>>>(dh, Wd, bd, be);
    dim3 g2(SS / 128, BB);
    k_scores<<<g2, 256, SMEM_DYN>>>(E, wa);
    k_softmax<<<BB, 256>>>(mask, attn);
    dim3 g4(DD / 128, BB, 8);
    k_context_part<<<g4, 128>>>(E, attn);
    k_context_red<<<BB, 256>>>(ctx);
}

// round 6
// speedup vs baseline: 4.4117x; 1.0020x over previous
#include <cuda_runtime.h>
#include <cuda_fp16.h>
#include <cstdint>
#include <cstring>

#define LL 2
#define BB 32
#define SS 2048
#define DD 1024

#if defined(__CUDA_ARCH_FEAT_SM103_ALL) || defined(__CUDA_ARCH_FEAT_SM100_ALL) || \
    defined(__CUDA_ARCH_SPECIFIC__) || defined(__CUDA_ARCH_FAMILY_SPECIFIC__)
#define TC_OK 1
#else
#define TC_OK 0
#endif

// scratch (allocation-free rule: __device__ globals)
__device__ float g_bias[BB * DD];      // dec_proj + b_dec + b_enc
__device__ float g_scores[BB * SS];    // pre-softmax scores
// W_enc^T packed as per-(pass,chunk) SW128-swizzled smem images:
// [pass 0..3][chunk 0..15] -> 64KB image = hi(256 f-rows x 64 k fp16, 32KB) | lo(32KB)
__device__ __align__(128) unsigned char g_Wpk[4 * 16 * 65536];
__device__ float g_cpart[8 * BB * DD];  // context partials over s-chunks

// ---------------- low-level helpers ----------------
__device__ __forceinline__ uint32_t h2u(__half2 h) {
    uint32_t u;
    memcpy(&u, &h, 4);
    return u;
}
__device__ __forceinline__ uint32_t smem_u32(const void* p) {
    uint32_t a;
    asm("{ .reg .u64 t; cvta.to.shared.u64 t, %1; cvt.u32.u64 %0, t; }"
        : "=r"(a) : "l"(p));
    return a;
}
__device__ __forceinline__ uint32_t elect1() {
    uint32_t p;
    asm volatile("{ .reg .pred p; elect.sync _|p, 0xFFFFFFFF; selp.b32 %0,1,0,p; }"
                 : "=r"(p));
    return p;
}
__device__ __forceinline__ void mbar_init(uint32_t a, uint32_t cnt) {
    asm volatile("mbarrier.init.shared.b64 [%0], %1;" :: "r"(a), "r"(cnt) : "memory");
}
__device__ __forceinline__ void mbar_wait(uint32_t a, int phase) {
    asm volatile(
        "{\n\t.reg .pred P;\n\t"
        "WL%=:\n\t"
        "mbarrier.try_wait.parity.acquire.cta.shared::cta.b64 P, [%0], %1, 0x989680;\n\t"
        "@P bra WD%=;\n\t"
        "bra WL%=;\n\t"
        "WD%=:\n\t}"
        :: "r"(a), "r"(phase) : "memory");
}
__device__ __forceinline__ void mbar_expect_tx(uint32_t a, uint32_t bytes) {
    asm volatile("mbarrier.arrive.expect_tx.shared.b64 _, [%0], %1;"
                 :: "r"(a), "r"(bytes) : "memory");
}
__device__ __forceinline__ void bulk_g2s(uint32_t dst, const void* src,
                                         uint32_t bytes, uint32_t mbar) {
    asm volatile(
        "cp.async.bulk.shared::cluster.global.mbarrier::complete_tx::bytes "
        "[%0], [%1], %2, [%3];"
        :: "r"(dst), "l"(src), "r"(bytes), "r"(mbar) : "memory");
}
__device__ __forceinline__ uint64_t mkdesc(uint32_t addr) {
    const uint64_t base = (uint64_t(2) << 61) | (uint64_t(1) << 46) |
                          (uint64_t(64) << 32) | (uint64_t(1) << 16);  // SW128 K-major
    return base | ((uint64_t)(addr >> 4) & 0x3FFF);
}
#if TC_OK
__device__ __forceinline__ void mma_f16(uint32_t d, uint64_t ad, uint64_t bd,
                                        uint32_t idesc, uint32_t en) {
    asm volatile(
        "{\n\t.reg .pred p;\n\tsetp.ne.u32 p, %4, 0;\n\t"
        "tcgen05.mma.cta_group::1.kind::f16 [%0], %1, %2, %3, {%5,%5,%5,%5}, p;\n\t}"
        :: "r"(d), "l"(ad), "l"(bd), "r"(idesc), "r"(en), "r"(0u) : "memory");
}
__device__ __forceinline__ void tc_commit(uint32_t mbar) {
    asm volatile(
        "tcgen05.commit.cta_group::1.mbarrier::arrive::one.shared::cluster.b64 [%0];"
        :: "r"(mbar) : "memory");
}
#endif

#define SWZ(o) ((o) ^ (((o) >> 3) & 0x70))

__device__ __forceinline__ float tanh_fast(float x) {
    return 1.f - __fdividef(2.f, __expf(2.f * x) + 1.f);
}

// ---------------- kernel 0: prep = W pack (blocks 0..1023) + decproj (1024..1055)
__global__ __launch_bounds__(256) void k_prep(const float* __restrict__ W,
                                              const float* __restrict__ dh,
                                              const float* __restrict__ Wd,
                                              const float* __restrict__ bd,
                                              const float* __restrict__ be) {
    const int tid = threadIdx.x;
    if (blockIdx.x < 1024) {
        // ---- pack W_enc[k][f] -> g_Wpk swizzled fp16 hi/lo images ----
        __shared__ float t[32][33];
        const int bx = blockIdx.x & 31;   // f tile
        const int by = blockIdx.x >> 5;   // k tile
        const int f0 = bx * 32, k0 = by * 32;
        const int tx = tid & 31, ty = tid >> 5;  // 32 x 8
#pragma unroll
        for (int j = 0; j < 4; j++)
            t[ty + j * 8][tx] = W[(size_t)(k0 + ty + j * 8) * DD + f0 + tx];
        __syncthreads();
        if (tid < 128) {
            const int fl = tid >> 2;        // 0..31 f within tile
            const int gk = tid & 3;         // 0..3 k-granule of 8
            float v[8];
#pragma unroll
            for (int j = 0; j < 8; j++) v[j] = t[gk * 8 + j][fl];
            uint4 hi, lo;
            {
                __half2 h0 = __floats2half2_rn(v[0], v[1]);
                __half2 h1 = __floats2half2_rn(v[2], v[3]);
                __half2 h2 = __floats2half2_rn(v[4], v[5]);
                __half2 h3 = __floats2half2_rn(v[6], v[7]);
                float2 a0 = __half22float2(h0), a1 = __half22float2(h1);
                float2 a2 = __half22float2(h2), a3 = __half22float2(h3);
                __half2 l0 = __floats2half2_rn(v[0] - a0.x, v[1] - a0.y);
                __half2 l1 = __floats2half2_rn(v[2] - a1.x, v[3] - a1.y);
                __half2 l2 = __floats2half2_rn(v[4] - a2.x, v[5] - a2.y);
                __half2 l3 = __floats2half2_rn(v[6] - a3.x, v[7] - a3.y);
                hi = make_uint4(h2u(h0), h2u(h1), h2u(h2), h2u(h3));
                lo = make_uint4(h2u(l0), h2u(l1), h2u(l2), h2u(l3));
            }
            const int f = f0 + fl, k = k0 + gk * 8;
            const int pass = f >> 8, frow = f & 255;
            const int chunk = k >> 6, kk = k & 63;
            const uint32_t base = (uint32_t)(pass * 16 + chunk) * 65536u;
            const uint32_t inner = SWZ((uint32_t)(frow * 128 + kk * 2));
            *(uint4*)(g_Wpk + base + inner) = hi;
            *(uint4*)(g_Wpk + base + 32768 + inner) = lo;
        }
    } else {
        // ---- decproj: g_bias = dh[-1] @ W_dec + b_dec + b_enc ----
        const int b = blockIdx.x - 1024;
        __shared__ float h[DD];
        for (int k = tid; k < DD; k += 256) h[k] = dh[(LL - 1) * BB * DD + b * DD + k];
        __syncthreads();
        const int f0 = tid * 4;
        float a0 = 0.f, a1 = 0.f, a2 = 0.f, a3 = 0.f;
#pragma unroll 4
        for (int k = 0; k < DD; k++) {
            float4 w = *(const float4*)(Wd + (size_t)k * DD + f0);
            float hk = h[k];
            a0 += hk * w.x; a1 += hk * w.y; a2 += hk * w.z; a3 += hk * w.w;
        }
        g_bias[b * DD + f0 + 0] = a0 + bd[f0 + 0] + be[f0 + 0];
        g_bias[b * DD + f0 + 1] = a1 + bd[f0 + 1] + be[f0 + 1];
        g_bias[b * DD + f0 + 2] = a2 + bd[f0 + 2] + be[f0 + 2];
        g_bias[b * DD + f0 + 3] = a3 + bd[f0 + 3] + be[f0 + 3];
    }
}

// ---------------- kernel 2: fused scores via tcgen05 3xFP16 ----------------
// D[s=128, f=256] in TMEM, K=64 per chunk (16 chunks/pass), 4 f-passes.
// A: manual fp32->fp16 hi/lo producer. B: cp.async.bulk of pre-packed images.
#define STAGE_BYTES 98304
#define OFF_A_HI 0
#define OFF_A_LO 16384
#define OFF_B 32768          /* hi 32KB | lo 32KB, one 64KB bulk copy */
#define CTL_BYTES 4096
#define SMEM_DYN (CTL_BYTES + 2 * STAGE_BYTES)

#if TC_OK
static constexpr uint32_t IDESC_F16 =
    (1u << 4) | ((256u / 8) << 17) | ((128u / 16) << 24);  // fp16 in, f32 acc
#endif

__global__ __launch_bounds__(256, 1) void k_scores(const float* __restrict__ E,
                                                   const float* __restrict__ wa) {
#if TC_OK
    extern __shared__ char sm[];
    const uint32_t smb = smem_u32(sm);
    const int tid = threadIdx.x;
    const int wid = tid >> 5;
    const int b = blockIdx.y;
    const int s0 = blockIdx.x * 128;

    const uint32_t free0 = smb + 16;   // stage-free (MMA commit) barriers
    const uint32_t free1 = smb + 24;
    const uint32_t fullB0 = smb + 32;  // B-arrived (bulk tx) barriers
    const uint32_t fullB1 = smb + 40;
    float* biasS = (float*)(sm + 1024);
    float* waS = (float*)(sm + 2048);
    float* red = (float*)(sm + 3072);

    if (wid == 0)
        asm volatile("tcgen05.alloc.cta_group::1.sync.aligned.shared::cta.b32 [%0], %1;"
                     :: "r"(smb), "r"(256) : "memory");
    if (tid == 0) {
        mbar_init(free0, 1); mbar_init(free1, 1);
        mbar_init(fullB0, 1); mbar_init(fullB1, 1);
    }
    __syncthreads();
    uint32_t tmem;
    asm("ld.shared.b32 %0, [%1];" : "=r"(tmem) : "r"(smb));

    int ph0 = 0, ph1 = 0;        // free-barrier phases (all threads)
    int pfb0 = 0, pfb1 = 0;      // fullB phases (used by thread 0 only)
    float acc = 0.f;
    const float* Eb = E + ((size_t)b * SS + s0) * DD;
    const int wg = wid >> 2, w4 = wid & 3, lane = tid & 31;

    for (int p = 0; p < 4; p++) {
        const int f0 = p * 256;
        for (int c = 0; c < 16; c++) {
            const int g = p * 16 + c;
            const int st = g & 1;
            if (g >= 2) {
                if (st == 0) { mbar_wait(free0, ph0); ph0 ^= 1; }
                else         { mbar_wait(free1, ph1); ph1 ^= 1; }
            }
            char* stg = sm + CTL_BYTES + st * STAGE_BYTES;
            const uint32_t sb = smb + CTL_BYTES + st * STAGE_BYTES;
            // ---- B: one bulk copy of the pre-packed 64KB image ----
            if (tid == 0) {
                uint32_t fb = st == 0 ? fullB0 : fullB1;
                mbar_expect_tx(fb, 65536u);
                bulk_g2s(sb + OFF_B, g_Wpk + (uint32_t)(p * 16 + c) * 65536u,
                         65536u, fb);
            }
            const int k0 = c * 64;
            // ---- A tile: E[s0..s0+127, k0..k0+63] -> fp16 hi/lo, SW128 ----
#pragma unroll
            for (int i = 0; i < 4; i++) {
                int idx = tid + i * 256;
                int row = idx >> 3, grp = idx & 7;
                const float* src = Eb + (size_t)row * DD + k0 + grp * 8;
                float4 v0 = *(const float4*)(src);
                float4 v1 = *(const float4*)(src + 4);
                __half2 h0 = __floats2half2_rn(v0.x, v0.y);
                __half2 h1 = __floats2half2_rn(v0.z, v0.w);
                __half2 h2 = __floats2half2_rn(v1.x, v1.y);
                __half2 h3 = __floats2half2_rn(v1.z, v1.w);
                float2 f0v = __half22float2(h0), f1v = __half22float2(h1);
                float2 f2v = __half22float2(h2), f3v = __half22float2(h3);
                __half2 l0 = __floats2half2_rn(v0.x - f0v.x, v0.y - f0v.y);
                __half2 l1 = __floats2half2_rn(v0.z - f1v.x, v0.w - f1v.y);
                __half2 l2 = __floats2half2_rn(v1.x - f2v.x, v1.y - f2v.y);
                __half2 l3 = __floats2half2_rn(v1.z - f3v.x, v1.w - f3v.y);
                uint32_t o = SWZ((uint32_t)(row * 128 + grp * 16));
                *(uint4*)(stg + OFF_A_HI + o) =
                    make_uint4(h2u(h0), h2u(h1), h2u(h2), h2u(h3));
                *(uint4*)(stg + OFF_A_LO + o) =
                    make_uint4(h2u(l0), h2u(l1), h2u(l2), h2u(l3));
            }
            asm volatile("fence.proxy.async.shared::cta;" ::: "memory");
            __syncthreads();
            if (tid == 0) {
                if (c == 0)
                    asm volatile("tcgen05.fence::after_thread_sync;" ::: "memory");
                // wait B arrival for this stage
                if (st == 0) { mbar_wait(fullB0, pfb0); pfb0 ^= 1; }
                else         { mbar_wait(fullB1, pfb1); pfb1 ^= 1; }
                uint64_t ah = mkdesc(sb + OFF_A_HI);
                uint64_t al = mkdesc(sb + OFF_A_LO);
                uint64_t bh = mkdesc(sb + OFF_B);
                uint64_t bl = mkdesc(sb + OFF_B + 32768);
#pragma unroll
                for (int kk = 0; kk < 4; kk++) {  // K=16 fp16 per step = +2 desc units
                    mma_f16(tmem, ah + 2 * kk, bh + 2 * kk, IDESC_F16,
                            (c > 0) || (kk > 0));
                    mma_f16(tmem, ah + 2 * kk, bl + 2 * kk, IDESC_F16, 1);
                    mma_f16(tmem, al + 2 * kk, bh + 2 * kk, IDESC_F16, 1);
                }
                tc_commit(st == 0 ? free0 : free1);
            }
        }
        // ---- pass epilogue ----
        biasS[tid] = g_bias[b * DD + f0 + tid];
        waS[tid] = wa[f0 + tid];
        mbar_wait(free1, ph1);  // last chunk (c=15, stage 1) commit; no flip
        asm volatile("tcgen05.fence::after_thread_sync;" ::: "memory");
        __syncthreads();
        const int colbase = wg * 128;
#pragma unroll
        for (int cb = 0; cb < 4; cb++) {
            uint32_t r[32];
            asm volatile(
                "tcgen05.ld.sync.aligned.32x32b.x32.b32 "
                "{%0, %1, %2, %3, %4, %5, %6, %7, "
                " %8, %9, %10, %11, %12, %13, %14, %15, "
                " %16, %17, %18, %19, %20, %21, %22, %23, "
                " %24, %25, %26, %27, %28, %29, %30, %31}, [%32];"
                : "=r"(r[0]), "=r"(r[1]), "=r"(r[2]), "=r"(r[3]),
                  "=r"(r[4]), "=r"(r[5]), "=r"(r[6]), "=r"(r[7]),
                  "=r"(r[8]), "=r"(r[9]), "=r"(r[10]), "=r"(r[11]),
                  "=r"(r[12]), "=r"(r[13]), "=r"(r[14]), "=r"(r[15]),
                  "=r"(r[16]), "=r"(r[17]), "=r"(r[18]), "=r"(r[19]),
                  "=r"(r[20]), "=r"(r[21]), "=r"(r[22]), "=r"(r[23]),
                  "=r"(r[24]), "=r"(r[25]), "=r"(r[26]), "=r"(r[27]),
                  "=r"(r[28]), "=r"(r[29]), "=r"(r[30]), "=r"(r[31])
                : "r"(tmem + colbase + cb * 32));
            asm volatile("tcgen05.wait::ld.sync.aligned;" ::: "memory");
#pragma unroll
            for (int j = 0; j < 32; j++) {
                int f = colbase + cb * 32 + j;
                float x = __uint_as_float(r[j]) + biasS[f];
                acc += tanh_fast(x) * waS[f];
            }
        }
        asm volatile("tcgen05.fence::before_thread_sync;" ::: "memory");
        __syncthreads();  // all LDTM done before next pass re-inits D
    }
    red[wg * 128 + w4 * 32 + lane] = acc;
    __syncthreads();
    if (tid < 128) g_scores[b * SS + s0 + tid] = red[tid] + red[tid + 128];
    __syncthreads();
    if (wid == 0)
        asm volatile("tcgen05.dealloc.cta_group::1.sync.aligned.b32 %0, %1;"
                     :: "r"(tmem), "r"(256));
#else
    // Generic-PTX fallback (never executes: exact sm_103a cubin is loaded).
    const int b = blockIdx.y;
    const int s = blockIdx.x * 128 + (threadIdx.x >> 1);
    const int fh = (threadIdx.x & 1) * 512;
    const float* Er = E + ((size_t)b * SS + s) * DD;
    float acc = 0.f;
    for (int f = fh; f < fh + 512; f++) {
        float e = g_bias[b * DD + f];
        const uint32_t base = (uint32_t)((f >> 8) * 16) * 65536u;
        const int frow = f & 255;
        for (int k = 0; k < DD; k++) {
            uint32_t off = (uint32_t)((k >> 6)) * 65536u +
                           SWZ((uint32_t)(frow * 128 + (k & 63) * 2));
            float w = __half2float(*(const __half*)(g_Wpk + base + off)) +
                      __half2float(*(const __half*)(g_Wpk + base + 32768 + off));
            e += Er[k] * w;
        }
        acc += tanhf(e) * wa[f];
    }
    acc += __shfl_xor_sync(0xffffffffu, acc, 1);
    if ((threadIdx.x & 1) == 0) g_scores[b * SS + s] = acc;
#endif
}

// ---------------- kernel 3: masked softmax over S ----------------
__global__ __launch_bounds__(256) void k_softmax(const int* __restrict__ mask,
                                                 float* __restrict__ attn) {
    const int b = blockIdx.x;
    const int tid = threadIdx.x;
    __shared__ float sc[SS];
    __shared__ float red[256];
    float lmax = -3.4e38f;
    for (int s = tid; s < SS; s += 256) {
        float v = (mask[b * SS + s] == 0) ? -1e10f : g_scores[b * SS + s];
        sc[s] = v;
        lmax = fmaxf(lmax, v);
    }
    red[tid] = lmax;
    __syncthreads();
    for (int o = 128; o > 0; o >>= 1) {
        if (tid < o) red[tid] = fmaxf(red[tid], red[tid + o]);
        __syncthreads();
    }
    float m = red[0];
    __syncthreads();
    float lsum = 0.f;
    for (int s = tid; s < SS; s += 256) {
        float e = __expf(sc[s] - m);
        sc[s] = e;
        lsum += e;
    }
    red[tid] = lsum;
    __syncthreads();
    for (int o = 128; o > 0; o >>= 1) {
        if (tid < o) red[tid] += red[tid + o];
        __syncthreads();
    }
    float inv = 1.f / red[0];
    for (int s = tid; s < SS; s += 256) attn[b * SS + s] = sc[s] * inv;
}

// ---------------- kernel 4a: context partials over 8 s-chunks ----------------
__global__ __launch_bounds__(128) void k_context_part(const float* __restrict__ E,
                                                      const float* __restrict__ attn) {
    const int b = blockIdx.y;
    const int sc = blockIdx.z;
    const int d = blockIdx.x * 128 + threadIdx.x;
    const int s0 = sc * 256;
    __shared__ float a[256];
    for (int i = threadIdx.x; i < 256; i += 128) a[i] = attn[b * SS + s0 + i];
    __syncthreads();
    const float* Eb = E + ((size_t)b * SS + s0) * DD + d;
    float acc[8];
#pragma unroll
    for (int j = 0; j < 8; j++) acc[j] = 0.f;
    for (int s = 0; s < 256; s += 8) {
#pragma unroll
        for (int j = 0; j < 8; j++)
            acc[j] += a[s + j] * Eb[(size_t)(s + j) * DD];
    }
    g_cpart[(sc * BB + b) * DD + d] =
        ((acc[0] + acc[1]) + (acc[2] + acc[3])) +
        ((acc[4] + acc[5]) + (acc[6] + acc[7]));
}

// ---------------- kernel 4b: reduce partials ----------------
__global__ __launch_bounds__(256) void k_context_red(float* __restrict__ ctx) {
    const int b = blockIdx.x;
    for (int d = threadIdx.x; d < DD; d += 256) {
        float s = 0.f;
#pragma unroll
        for (int sc = 0; sc < 8; sc++) s += g_cpart[(sc * BB + b) * DD + d];
        ctx[b * DD + d] = s;
    }
}

extern "C" void kernel_launch(void* const* d_in, const int* in_sizes, int n_in,
                              void* d_out, int out_size) {
    const float* dh   = (const float*)d_in[0];  // [2,32,1024]
    const float* E    = (const float*)d_in[1];  // [32,2048,1024]
    const int*   mask = (const int*)d_in[2];    // [32,2048]
    const float* Wd   = (const float*)d_in[3];  // [1024,1024]
    const float* bd   = (const float*)d_in[4];  // [1024]
    const float* We   = (const float*)d_in[5];  // [1024,1024]
    const float* be   = (const float*)d_in[6];  // [1024]
    const float* wa   = (const float*)d_in[7];  // [1024,1]
    (void)d_in[8];                               // b_att: softmax-invariant

    float* out  = (float*)d_out;
    float* ctx  = out;            // context: B*D
    float* attn = out + BB * DD;  // attn:    B*S

    cudaFuncSetAttribute(k_scores, cudaFuncAttributeMaxDynamicSharedMemorySize,
                         SMEM_DYN);

    k_prep<<<1024 + BB, 256>>>(We, dh, Wd, bd, be);
    dim3 g2(SS / 128, BB);
    k_scores<<<g2, 256, SMEM_DYN>>>(E, wa);
    k_softmax<<<BB, 256>>>(mask, attn);
    dim3 g4(DD / 128, BB, 8);
    k_context_part<<<g4, 128>>>(E, attn);
    k_context_red<<<BB, 256>>>(ctx);
}

// round 7
// speedup vs baseline: 4.4395x; 1.0063x over previous
#include <cuda_runtime.h>
#include <cuda_fp16.h>
#include <cstdint>
#include <cstring>

#define LL 2
#define BB 32
#define SS 2048
#define DD 1024

#if defined(__CUDA_ARCH_FEAT_SM103_ALL) || defined(__CUDA_ARCH_FEAT_SM100_ALL) || \
    defined(__CUDA_ARCH_SPECIFIC__) || defined(__CUDA_ARCH_FAMILY_SPECIFIC__)
#define TC_OK 1
#else
#define TC_OK 0
#endif

// scratch (allocation-free rule: __device__ globals)
__device__ float g_bias[BB * DD];      // dec_proj + b_dec + b_enc
__device__ float g_scores[BB * SS];    // pre-softmax scores
// W_enc^T packed as per-(pass,chunk) SW128-swizzled smem images:
// [pass 0..3][chunk 0..15] -> 64KB image = hi(256 f-rows x 64 k fp16, 32KB) | lo(32KB)
__device__ __align__(128) unsigned char g_Wpk[4 * 16 * 65536];
__device__ float g_cpart[8 * BB * DD];  // context partials over s-chunks

// ---------------- low-level helpers ----------------
__device__ __forceinline__ uint32_t h2u(__half2 h) {
    uint32_t u;
    memcpy(&u, &h, 4);
    return u;
}
__device__ __forceinline__ uint32_t smem_u32(const void* p) {
    uint32_t a;
    asm("{ .reg .u64 t; cvta.to.shared.u64 t, %1; cvt.u32.u64 %0, t; }"
        : "=r"(a) : "l"(p));
    return a;
}
__device__ __forceinline__ uint32_t elect1() {
    uint32_t p;
    asm volatile("{ .reg .pred p; elect.sync _|p, 0xFFFFFFFF; selp.b32 %0,1,0,p; }"
                 : "=r"(p));
    return p;
}
__device__ __forceinline__ void mbar_init(uint32_t a, uint32_t cnt) {
    asm volatile("mbarrier.init.shared.b64 [%0], %1;" :: "r"(a), "r"(cnt) : "memory");
}
__device__ __forceinline__ void mbar_wait(uint32_t a, int phase) {
    asm volatile(
        "{\n\t.reg .pred P;\n\t"
        "WL%=:\n\t"
        "mbarrier.try_wait.parity.acquire.cta.shared::cta.b64 P, [%0], %1, 0x989680;\n\t"
        "@P bra WD%=;\n\t"
        "bra WL%=;\n\t"
        "WD%=:\n\t}"
        :: "r"(a), "r"(phase) : "memory");
}
__device__ __forceinline__ void mbar_expect_tx(uint32_t a, uint32_t bytes) {
    asm volatile("mbarrier.arrive.expect_tx.shared.b64 _, [%0], %1;"
                 :: "r"(a), "r"(bytes) : "memory");
}
__device__ __forceinline__ void bulk_g2s(uint32_t dst, const void* src,
                                         uint32_t bytes, uint32_t mbar) {
    asm volatile(
        "cp.async.bulk.shared::cluster.global.mbarrier::complete_tx::bytes "
        "[%0], [%1], %2, [%3];"
        :: "r"(dst), "l"(src), "r"(bytes), "r"(mbar) : "memory");
}
__device__ __forceinline__ uint64_t mkdesc(uint32_t addr) {
    const uint64_t base = (uint64_t(2) << 61) | (uint64_t(1) << 46) |
                          (uint64_t(64) << 32) | (uint64_t(1) << 16);  // SW128 K-major
    return base | ((uint64_t)(addr >> 4) & 0x3FFF);
}
#if TC_OK
__device__ __forceinline__ void mma_f16(uint32_t d, uint64_t ad, uint64_t bd,
                                        uint32_t idesc, uint32_t en) {
    asm volatile(
        "{\n\t.reg .pred p;\n\tsetp.ne.u32 p, %4, 0;\n\t"
        "tcgen05.mma.cta_group::1.kind::f16 [%0], %1, %2, %3, {%5,%5,%5,%5}, p;\n\t}"
        :: "r"(d), "l"(ad), "l"(bd), "r"(idesc), "r"(en), "r"(0u) : "memory");
}
__device__ __forceinline__ void tc_commit(uint32_t mbar) {
    asm volatile(
        "tcgen05.commit.cta_group::1.mbarrier::arrive::one.shared::cluster.b64 [%0];"
        :: "r"(mbar) : "memory");
}
#endif

#define SWZ(o) ((o) ^ (((o) >> 3) & 0x70))

__device__ __forceinline__ float tanh_fast(float x) {
    return 1.f - __fdividef(2.f, __expf(2.f * x) + 1.f);
}

// ---------------- kernel 0: prep = W pack (blocks 0..1023) + decproj (1024..1055)
__global__ __launch_bounds__(256) void k_prep(const float* __restrict__ W,
                                              const float* __restrict__ dh,
                                              const float* __restrict__ Wd,
                                              const float* __restrict__ bd,
                                              const float* __restrict__ be) {
    const int tid = threadIdx.x;
    if (blockIdx.x < 1024) {
        // ---- pack W_enc[k][f] -> g_Wpk swizzled fp16 hi/lo images ----
        __shared__ float t[32][33];
        const int bx = blockIdx.x & 31;   // f tile
        const int by = blockIdx.x >> 5;   // k tile
        const int f0 = bx * 32, k0 = by * 32;
        const int tx = tid & 31, ty = tid >> 5;  // 32 x 8
#pragma unroll
        for (int j = 0; j < 4; j++)
            t[ty + j * 8][tx] = W[(size_t)(k0 + ty + j * 8) * DD + f0 + tx];
        __syncthreads();
        if (tid < 128) {
            const int fl = tid >> 2;        // 0..31 f within tile
            const int gk = tid & 3;         // 0..3 k-granule of 8
            float v[8];
#pragma unroll
            for (int j = 0; j < 8; j++) v[j] = t[gk * 8 + j][fl];
            uint4 hi, lo;
            {
                __half2 h0 = __floats2half2_rn(v[0], v[1]);
                __half2 h1 = __floats2half2_rn(v[2], v[3]);
                __half2 h2 = __floats2half2_rn(v[4], v[5]);
                __half2 h3 = __floats2half2_rn(v[6], v[7]);
                float2 a0 = __half22float2(h0), a1 = __half22float2(h1);
                float2 a2 = __half22float2(h2), a3 = __half22float2(h3);
                __half2 l0 = __floats2half2_rn(v[0] - a0.x, v[1] - a0.y);
                __half2 l1 = __floats2half2_rn(v[2] - a1.x, v[3] - a1.y);
                __half2 l2 = __floats2half2_rn(v[4] - a2.x, v[5] - a2.y);
                __half2 l3 = __floats2half2_rn(v[6] - a3.x, v[7] - a3.y);
                hi = make_uint4(h2u(h0), h2u(h1), h2u(h2), h2u(h3));
                lo = make_uint4(h2u(l0), h2u(l1), h2u(l2), h2u(l3));
            }
            const int f = f0 + fl, k = k0 + gk * 8;
            const int pass = f >> 8, frow = f & 255;
            const int chunk = k >> 6, kk = k & 63;
            const uint32_t base = (uint32_t)(pass * 16 + chunk) * 65536u;
            const uint32_t inner = SWZ((uint32_t)(frow * 128 + kk * 2));
            *(uint4*)(g_Wpk + base + inner) = hi;
            *(uint4*)(g_Wpk + base + 32768 + inner) = lo;
        }
    } else {
        // ---- decproj: g_bias = dh[-1] @ W_dec + b_dec + b_enc ----
        const int b = blockIdx.x - 1024;
        __shared__ float h[DD];
        for (int k = tid; k < DD; k += 256) h[k] = dh[(LL - 1) * BB * DD + b * DD + k];
        __syncthreads();
        const int f0 = tid * 4;
        float a0 = 0.f, a1 = 0.f, a2 = 0.f, a3 = 0.f;
#pragma unroll 4
        for (int k = 0; k < DD; k++) {
            float4 w = *(const float4*)(Wd + (size_t)k * DD + f0);
            float hk = h[k];
            a0 += hk * w.x; a1 += hk * w.y; a2 += hk * w.z; a3 += hk * w.w;
        }
        g_bias[b * DD + f0 + 0] = a0 + bd[f0 + 0] + be[f0 + 0];
        g_bias[b * DD + f0 + 1] = a1 + bd[f0 + 1] + be[f0 + 1];
        g_bias[b * DD + f0 + 2] = a2 + bd[f0 + 2] + be[f0 + 2];
        g_bias[b * DD + f0 + 3] = a3 + bd[f0 + 3] + be[f0 + 3];
    }
}

// ---------------- kernel 2: fused scores via tcgen05 3xFP16 ----------------
// D[s=128, f=256] in TMEM, K=64 per chunk (16 chunks/pass), 4 f-passes.
// A: manual fp32->fp16 hi/lo producer. B: cp.async.bulk of pre-packed images.
#define STAGE_BYTES 98304
#define OFF_A_HI 0
#define OFF_A_LO 16384
#define OFF_B 32768          /* hi 32KB | lo 32KB, one 64KB bulk copy */
#define CTL_BYTES 4096
#define SMEM_DYN (CTL_BYTES + 2 * STAGE_BYTES)

#if TC_OK
static constexpr uint32_t IDESC_F16 =
    (1u << 4) | ((256u / 8) << 17) | ((128u / 16) << 24);  // fp16 in, f32 acc
#endif

__global__ __launch_bounds__(256, 1) void k_scores(const float* __restrict__ E,
                                                   const float* __restrict__ wa) {
#if TC_OK
    extern __shared__ char sm[];
    const uint32_t smb = smem_u32(sm);
    const int tid = threadIdx.x;
    const int wid = tid >> 5;
    const int b = blockIdx.y;
    const int s0 = blockIdx.x * 128;

    const uint32_t free0 = smb + 16;   // stage-free (MMA commit) barriers
    const uint32_t free1 = smb + 24;
    const uint32_t fullB0 = smb + 32;  // B-arrived (bulk tx) barriers
    const uint32_t fullB1 = smb + 40;
    float* biasS = (float*)(sm + 1024);
    float* waS = (float*)(sm + 2048);
    float* red = (float*)(sm + 3072);

    if (wid == 0)
        asm volatile("tcgen05.alloc.cta_group::1.sync.aligned.shared::cta.b32 [%0], %1;"
                     :: "r"(smb), "r"(256) : "memory");
    if (tid == 0) {
        mbar_init(free0, 1); mbar_init(free1, 1);
        mbar_init(fullB0, 1); mbar_init(fullB1, 1);
    }
    __syncthreads();
    uint32_t tmem;
    asm("ld.shared.b32 %0, [%1];" : "=r"(tmem) : "r"(smb));

    int ph0 = 0, ph1 = 0;        // free-barrier phases (all threads)
    int pfb0 = 0, pfb1 = 0;      // fullB phases (used by thread 0 only)
    float acc = 0.f;
    const float* Eb = E + ((size_t)b * SS + s0) * DD;
    const int wg = wid >> 2, w4 = wid & 3, lane = tid & 31;

    for (int p = 0; p < 4; p++) {
        const int f0 = p * 256;
        for (int c = 0; c < 16; c++) {
            const int g = p * 16 + c;
            const int st = g & 1;
            if (g >= 2) {
                if (st == 0) { mbar_wait(free0, ph0); ph0 ^= 1; }
                else         { mbar_wait(free1, ph1); ph1 ^= 1; }
            }
            char* stg = sm + CTL_BYTES + st * STAGE_BYTES;
            const uint32_t sb = smb + CTL_BYTES + st * STAGE_BYTES;
            // ---- B: one bulk copy of the pre-packed 64KB image ----
            if (tid == 0) {
                uint32_t fb = st == 0 ? fullB0 : fullB1;
                mbar_expect_tx(fb, 65536u);
                bulk_g2s(sb + OFF_B, g_Wpk + (uint32_t)(p * 16 + c) * 65536u,
                         65536u, fb);
            }
            const int k0 = c * 64;
            // ---- A tile: E[s0..s0+127, k0..k0+63] -> fp16 hi/lo, SW128 ----
#pragma unroll
            for (int i = 0; i < 4; i++) {
                int idx = tid + i * 256;
                int row = idx >> 3, grp = idx & 7;
                const float* src = Eb + (size_t)row * DD + k0 + grp * 8;
                float4 v0 = *(const float4*)(src);
                float4 v1 = *(const float4*)(src + 4);
                __half2 h0 = __floats2half2_rn(v0.x, v0.y);
                __half2 h1 = __floats2half2_rn(v0.z, v0.w);
                __half2 h2 = __floats2half2_rn(v1.x, v1.y);
                __half2 h3 = __floats2half2_rn(v1.z, v1.w);
                float2 f0v = __half22float2(h0), f1v = __half22float2(h1);
                float2 f2v = __half22float2(h2), f3v = __half22float2(h3);
                __half2 l0 = __floats2half2_rn(v0.x - f0v.x, v0.y - f0v.y);
                __half2 l1 = __floats2half2_rn(v0.z - f1v.x, v0.w - f1v.y);
                __half2 l2 = __floats2half2_rn(v1.x - f2v.x, v1.y - f2v.y);
                __half2 l3 = __floats2half2_rn(v1.z - f3v.x, v1.w - f3v.y);
                uint32_t o = SWZ((uint32_t)(row * 128 + grp * 16));
                *(uint4*)(stg + OFF_A_HI + o) =
                    make_uint4(h2u(h0), h2u(h1), h2u(h2), h2u(h3));
                *(uint4*)(stg + OFF_A_LO + o) =
                    make_uint4(h2u(l0), h2u(l1), h2u(l2), h2u(l3));
            }
            asm volatile("fence.proxy.async.shared::cta;" ::: "memory");
            __syncthreads();
            if (tid == 0) {
                if (c == 0)
                    asm volatile("tcgen05.fence::after_thread_sync;" ::: "memory");
                // wait B arrival for this stage
                if (st == 0) { mbar_wait(fullB0, pfb0); pfb0 ^= 1; }
                else         { mbar_wait(fullB1, pfb1); pfb1 ^= 1; }
                uint64_t ah = mkdesc(sb + OFF_A_HI);
                uint64_t al = mkdesc(sb + OFF_A_LO);
                uint64_t bh = mkdesc(sb + OFF_B);
                uint64_t bl = mkdesc(sb + OFF_B + 32768);
#pragma unroll
                for (int kk = 0; kk < 4; kk++) {  // K=16 fp16 per step = +2 desc units
                    mma_f16(tmem, ah + 2 * kk, bh + 2 * kk, IDESC_F16,
                            (c > 0) || (kk > 0));
                    mma_f16(tmem, ah + 2 * kk, bl + 2 * kk, IDESC_F16, 1);
                    mma_f16(tmem, al + 2 * kk, bh + 2 * kk, IDESC_F16, 1);
                }
                tc_commit(st == 0 ? free0 : free1);
            }
        }
        // ---- pass epilogue ----
        biasS[tid] = g_bias[b * DD + f0 + tid];
        waS[tid] = wa[f0 + tid];
        mbar_wait(free1, ph1);  // last chunk (c=15, stage 1) commit; no flip
        asm volatile("tcgen05.fence::after_thread_sync;" ::: "memory");
        __syncthreads();
        const int colbase = wg * 128;
#pragma unroll
        for (int cb = 0; cb < 4; cb++) {
            uint32_t r[32];
            asm volatile(
                "tcgen05.ld.sync.aligned.32x32b.x32.b32 "
                "{%0, %1, %2, %3, %4, %5, %6, %7, "
                " %8, %9, %10, %11, %12, %13, %14, %15, "
                " %16, %17, %18, %19, %20, %21, %22, %23, "
                " %24, %25, %26, %27, %28, %29, %30, %31}, [%32];"
                : "=r"(r[0]), "=r"(r[1]), "=r"(r[2]), "=r"(r[3]),
                  "=r"(r[4]), "=r"(r[5]), "=r"(r[6]), "=r"(r[7]),
                  "=r"(r[8]), "=r"(r[9]), "=r"(r[10]), "=r"(r[11]),
                  "=r"(r[12]), "=r"(r[13]), "=r"(r[14]), "=r"(r[15]),
                  "=r"(r[16]), "=r"(r[17]), "=r"(r[18]), "=r"(r[19]),
                  "=r"(r[20]), "=r"(r[21]), "=r"(r[22]), "=r"(r[23]),
                  "=r"(r[24]), "=r"(r[25]), "=r"(r[26]), "=r"(r[27]),
                  "=r"(r[28]), "=r"(r[29]), "=r"(r[30]), "=r"(r[31])
                : "r"(tmem + colbase + cb * 32));
            asm volatile("tcgen05.wait::ld.sync.aligned;" ::: "memory");
#pragma unroll
            for (int j = 0; j < 32; j++) {
                int f = colbase + cb * 32 + j;
                float x = __uint_as_float(r[j]) + biasS[f];
                acc += tanh_fast(x) * waS[f];
            }
        }
        asm volatile("tcgen05.fence::before_thread_sync;" ::: "memory");
        __syncthreads();  // all LDTM done before next pass re-inits D
    }
    red[wg * 128 + w4 * 32 + lane] = acc;
    __syncthreads();
    if (tid < 128) g_scores[b * SS + s0 + tid] = red[tid] + red[tid + 128];
    __syncthreads();
    if (wid == 0)
        asm volatile("tcgen05.dealloc.cta_group::1.sync.aligned.b32 %0, %1;"
                     :: "r"(tmem), "r"(256));
#else
    // Generic-PTX fallback (never executes: exact sm_103a cubin is loaded).
    const int b = blockIdx.y;
    const int s = blockIdx.x * 128 + (threadIdx.x >> 1);
    const int fh = (threadIdx.x & 1) * 512;
    const float* Er = E + ((size_t)b * SS + s) * DD;
    float acc = 0.f;
    for (int f = fh; f < fh + 512; f++) {
        float e = g_bias[b * DD + f];
        const uint32_t base = (uint32_t)((f >> 8) * 16) * 65536u;
        const int frow = f & 255;
        for (int k = 0; k < DD; k++) {
            uint32_t off = (uint32_t)((k >> 6)) * 65536u +
                           SWZ((uint32_t)(frow * 128 + (k & 63) * 2));
            float w = __half2float(*(const __half*)(g_Wpk + base + off)) +
                      __half2float(*(const __half*)(g_Wpk + base + 32768 + off));
            e += Er[k] * w;
        }
        acc += tanhf(e) * wa[f];
    }
    acc += __shfl_xor_sync(0xffffffffu, acc, 1);
    if ((threadIdx.x & 1) == 0) g_scores[b * SS + s] = acc;
#endif
}

// ---------------- kernel 3: masked softmax over S ----------------
__global__ __launch_bounds__(256) void k_softmax(const int* __restrict__ mask,
                                                 float* __restrict__ attn) {
    const int b = blockIdx.x;
    const int tid = threadIdx.x;
    __shared__ float sc[SS];
    __shared__ float red[256];
    float lmax = -3.4e38f;
    for (int s = tid; s < SS; s += 256) {
        float v = (mask[b * SS + s] == 0) ? -1e10f : g_scores[b * SS + s];
        sc[s] = v;
        lmax = fmaxf(lmax, v);
    }
    red[tid] = lmax;
    __syncthreads();
    for (int o = 128; o > 0; o >>= 1) {
        if (tid < o) red[tid] = fmaxf(red[tid], red[tid + o]);
        __syncthreads();
    }
    float m = red[0];
    __syncthreads();
    float lsum = 0.f;
    for (int s = tid; s < SS; s += 256) {
        float e = __expf(sc[s] - m);
        sc[s] = e;
        lsum += e;
    }
    red[tid] = lsum;
    __syncthreads();
    for (int o = 128; o > 0; o >>= 1) {
        if (tid < o) red[tid] += red[tid + o];
        __syncthreads();
    }
    float inv = 1.f / red[0];
    for (int s = tid; s < SS; s += 256) attn[b * SS + s] = sc[s] * inv;
}

// ---------------- kernel 4a: context partials over 8 s-chunks ----------------
__global__ __launch_bounds__(128) void k_context_part(const float* __restrict__ E,
                                                      const float* __restrict__ attn) {
    const int b = blockIdx.y;
    const int sc = blockIdx.z;
    const int d = blockIdx.x * 128 + threadIdx.x;
    const int s0 = sc * 256;
    __shared__ float a[256];
    for (int i = threadIdx.x; i < 256; i += 128) a[i] = attn[b * SS + s0 + i];
    __syncthreads();
    const float* Eb = E + ((size_t)b * SS + s0) * DD + d;
    float acc[8];
#pragma unroll
    for (int j = 0; j < 8; j++) acc[j] = 0.f;
    for (int s = 0; s < 256; s += 8) {
#pragma unroll
        for (int j = 0; j < 8; j++)
            acc[j] += a[s + j] * Eb[(size_t)(s + j) * DD];
    }
    g_cpart[(sc * BB + b) * DD + d] =
        ((acc[0] + acc[1]) + (acc[2] + acc[3])) +
        ((acc[4] + acc[5]) + (acc[6] + acc[7]));
}

// ---------------- kernel 4b: reduce partials ----------------
__global__ __launch_bounds__(256) void k_context_red(float* __restrict__ ctx) {
    const int b = blockIdx.x;
    for (int d = threadIdx.x; d < DD; d += 256) {
        float s = 0.f;
#pragma unroll
        for (int sc = 0; sc < 8; sc++) s += g_cpart[(sc * BB + b) * DD + d];
        ctx[b * DD + d] = s;
    }
}

extern "C" void kernel_launch(void* const* d_in, const int* in_sizes, int n_in,
                              void* d_out, int out_size) {
    const float* dh   = (const float*)d_in[0];  // [2,32,1024]
    const float* E    = (const float*)d_in[1];  // [32,2048,1024]
    const int*   mask = (const int*)d_in[2];    // [32,2048]
    const float* Wd   = (const float*)d_in[3];  // [1024,1024]
    const float* bd   = (const float*)d_in[4];  // [1024]
    const float* We   = (const float*)d_in[5];  // [1024,1024]
    const float* be   = (const float*)d_in[6];  // [1024]
    const float* wa   = (const float*)d_in[7];  // [1024,1]
    (void)d_in[8];                               // b_att: softmax-invariant

    float* out  = (float*)d_out;
    float* ctx  = out;            // context: B*D
    float* attn = out + BB * DD;  // attn:    B*S

    cudaFuncSetAttribute(k_scores, cudaFuncAttributeMaxDynamicSharedMemorySize,
                         SMEM_DYN);

    k_prep<<<1024 + BB, 256>>>(We, dh, Wd, bd, be);
    dim3 g2(SS / 128, BB);
    k_scores<<<g2, 256, SMEM_DYN>>>(E, wa);
    k_softmax<<<BB, 256>>>(mask, attn);
    dim3 g4(DD / 128, BB, 8);
    k_context_part<<<g4, 128>>>(E, attn);
    k_context_red<<<BB, 256>>>(ctx);
}